// round 1
// baseline (speedup 1.0000x reference)
#include <cuda_runtime.h>

#define NMAX 4096
#define MMAX 8192
#define NCAM 6
#define NCLS 10
#define NSL  8
#define IMGW 1600
#define IMGH 900

// ---- device scratch (static, zero-initialized at module load; no allocs) ----
__device__ float4 g_proj  [NCAM * NMAX];
__device__ float  g_parea [NCAM * NMAX];
__device__ float  g_validf[NCAM * NMAX];
__device__ int    g_vlist [NCAM * NMAX];
__device__ int    g_vcount[NCAM];
__device__ int    g_boff  [NCAM * NCLS + 1];
__device__ float4 g_sbox  [MMAX];
__device__ float2 g_sas   [MMAX];   // (det_area, score)
__device__ float  g_part  [NCAM * NSL * NMAX * NCLS];  // partial class sums

// ============================================================================
// Kernel 1: project 3D boxes to per-camera 2D boxes + validity
// ============================================================================
__global__ void proj_kernel(const float* __restrict__ boxes,
                            const float* __restrict__ iam,   // (1,6,4,4)
                            const float* __restrict__ lam,   // (1,4,4)
                            const float* __restrict__ l2i,   // (1,6,4,4)
                            int N) {
    int n = blockIdx.x * blockDim.x + threadIdx.x;
    if (n >= N) return;

    float bx = boxes[n*7+0], by = boxes[n*7+1], bz = boxes[n*7+2];
    float ddx = boxes[n*7+3], ddy = boxes[n*7+4], ddz = boxes[n*7+5];
    float yaw = boxes[n*7+6];
    float sn, cs;
    sincosf(yaw, &sn, &cs);

    // lidar aug: p = inv(R) @ (corner - t)
    float r00=lam[0], r01=lam[1], r02=lam[2],  t0=lam[3];
    float r10=lam[4], r11=lam[5], r12=lam[6],  t1=lam[7];
    float r20=lam[8], r21=lam[9], r22=lam[10], t2=lam[11];
    float A = r11*r22 - r12*r21;
    float B = r02*r21 - r01*r22;
    float C = r01*r12 - r02*r11;
    float D = r12*r20 - r10*r22;
    float E = r00*r22 - r02*r20;
    float F = r02*r10 - r00*r12;
    float G = r10*r21 - r11*r20;
    float H = r01*r20 - r00*r21;
    float I = r00*r11 - r01*r10;
    float det = r00*A + r01*D + r02*G;
    float id  = __fdiv_rn(1.0f, det);
    float i00=A*id, i01=B*id, i02=C*id;
    float i10=D*id, i11=E*id, i12=F*id;
    float i20=G*id, i21=H*id, i22=I*id;

    float px[8], py[8], pz[8];
    #pragma unroll
    for (int k = 0; k < 8; k++) {
        float lx = ((k & 1) ? 0.5f : -0.5f) * ddx;
        float ly = ((k & 2) ? 0.5f : -0.5f) * ddy;
        float lz = ((k & 4) ? 0.5f : -0.5f) * ddz;
        // corners @ rot(yaw): x' = x c - y s ; y' = x s + y c
        float wx = lx*cs - ly*sn + bx;
        float wy = lx*sn + ly*cs + by;
        float wz = lz + bz;
        float ax = wx - t0, ay = wy - t1, az = wz - t2;
        px[k] = i00*ax + i01*ay + i02*az;
        py[k] = i10*ax + i11*ay + i12*az;
        pz[k] = i20*ax + i21*ay + i22*az;
    }

    for (int cam = 0; cam < NCAM; cam++) {
        const float* L  = l2i + cam*16;
        const float* Ai = iam + cam*16;
        int mnx =  0x7fffffff, mny =  0x7fffffff;
        int mxx = -0x7fffffff-1, mxy = -0x7fffffff-1;
        #pragma unroll
        for (int k = 0; k < 8; k++) {
            float cx  = L[0]*px[k] + L[1]*py[k] + L[2]*pz[k]  + L[3];
            float cyv = L[4]*px[k] + L[5]*py[k] + L[6]*pz[k]  + L[7];
            float cz  = L[8]*px[k] + L[9]*py[k] + L[10]*pz[k] + L[11];
            float z = fminf(fmaxf(cz, 1e-5f), 100000.0f);
            float x = __fdiv_rn(cx, z);     // IEEE: int truncation boundaries matter
            float y = __fdiv_rn(cyv, z);
            float ux = Ai[0]*x + Ai[1]*y + Ai[2]*z + Ai[3];
            float uy = Ai[4]*x + Ai[5]*y + Ai[6]*z + Ai[7];
            int ixi = (int)ux;  ixi = min(max(ixi, 0), IMGW);   // cvt.rzi saturates like ref
            int iyi = (int)uy;  iyi = min(max(iyi, 0), IMGH);
            mnx = min(mnx, ixi); mxx = max(mxx, ixi);
            mny = min(mny, iyi); mxy = max(mxy, iyi);
        }
        float fx1 = (float)mnx, fy1 = (float)mny;
        float fx2 = (float)mxx, fy2 = (float)mxy;
        g_proj  [cam*N + n] = make_float4(fx1, fy1, fx2, fy2);
        g_parea [cam*N + n] = (fx2 - fx1) * (fy2 - fy1);
        g_validf[cam*N + n] = ((mxx - mnx) > 0 && (mxy - mny) > 0) ? 1.0f : 0.0f;
    }
}

// ============================================================================
// Kernel 2: stable compaction of valid boxes per camera (block per cam)
// ============================================================================
__global__ void compact_valid(int N) {
    int cam = blockIdx.x;
    int tid = threadIdx.x;
    __shared__ int wcnt[8], woff[8], stot;
    int base = 0;
    for (int start = 0; start < N; start += 256) {
        int n = start + tid;
        bool f = (n < N) && (g_validf[cam*N + n] > 0.0f);
        unsigned bal = __ballot_sync(0xffffffffu, f);
        int wid = tid >> 5, lane = tid & 31;
        if (lane == 0) wcnt[wid] = __popc(bal);
        __syncthreads();
        if (tid == 0) { int s = 0; for (int w = 0; w < 8; w++) { woff[w] = s; s += wcnt[w]; } stot = s; }
        __syncthreads();
        if (f) {
            int r = base + woff[wid] + __popc(bal & ((1u << lane) - 1u));
            g_vlist[cam*N + r] = n;
        }
        base += stot;
        __syncthreads();
    }
    if (tid == 0) g_vcount[cam] = base;
}

// ============================================================================
// Kernel 3: histogram + exclusive prefix over 60 (cam,class) buckets
// ============================================================================
__global__ void hist_kernel(const int* __restrict__ lab, const int* __restrict__ bat,
                            const int* __restrict__ camix, int M) {
    __shared__ int h[NCAM * NCLS];
    int tid = threadIdx.x;
    for (int k = tid; k < NCAM * NCLS; k += 256) h[k] = 0;
    __syncthreads();
    for (int m = tid; m < M; m += 256) {
        int l = lab[m], b = bat[m], c = camix[m];
        if (b == 0 && l >= 1 && l <= NCLS && c >= 0 && c < NCAM)
            atomicAdd(&h[c * NCLS + l - 1], 1);
    }
    __syncthreads();
    if (tid == 0) {
        int s = 0;
        for (int k = 0; k < NCAM * NCLS; k++) { g_boff[k] = s; s += h[k]; }
        g_boff[NCAM * NCLS] = s;
    }
}

// ============================================================================
// Kernel 4: stable scatter of dets into sorted bucket order (block per bucket)
// ============================================================================
__global__ void scatter_kernel(const float* __restrict__ dbox, const int* __restrict__ lab,
                               const float* __restrict__ dsc, const int* __restrict__ bat,
                               const int* __restrict__ camix, int M) {
    int bkt = blockIdx.x;
    int tid = threadIdx.x;
    __shared__ int wcnt[8], woff[8], stot;
    int base = g_boff[bkt];
    for (int start = 0; start < M; start += 256) {
        int m = start + tid;
        bool f = false;
        if (m < M) {
            int l = lab[m], b = bat[m], c = camix[m];
            f = (b == 0 && l >= 1 && l <= NCLS && c >= 0 && c < NCAM &&
                 (c * NCLS + l - 1) == bkt);
        }
        unsigned bal = __ballot_sync(0xffffffffu, f);
        int wid = tid >> 5, lane = tid & 31;
        if (lane == 0) wcnt[wid] = __popc(bal);
        __syncthreads();
        if (tid == 0) { int s = 0; for (int w = 0; w < 8; w++) { woff[w] = s; s += wcnt[w]; } stot = s; }
        __syncthreads();
        if (f) {
            int r = base + woff[wid] + __popc(bal & ((1u << lane) - 1u));
            float x1 = dbox[m*4+0], y1 = dbox[m*4+1];
            float x2 = dbox[m*4+2], y2 = dbox[m*4+3];
            g_sbox[r] = make_float4(x1, y1, x2, y2);
            g_sas[r]  = make_float2((x2 - x1) * (y2 - y1), dsc[m]);
        }
        base += stot;
        __syncthreads();
    }
}

// ============================================================================
// Kernel 5: main IoU-weighted class accumulation over valid (cam,box) pairs
//   grid: (ceil(N/256), NCAM, NSL). One thread = one (valid pair, det slice).
//   All lanes share cam -> uniform bucket ranges, broadcast det loads.
// ============================================================================
__global__ void main_kernel(int N) {
    int cam = blockIdx.y;
    int sl  = blockIdx.z;
    int i   = blockIdx.x * blockDim.x + threadIdx.x;
    if (i >= g_vcount[cam]) return;
    int n = g_vlist[cam*N + i];

    float4 pb = g_proj [cam*N + n];
    float  pa = g_parea[cam*N + n];

    float acc[NCLS];
    #pragma unroll
    for (int cls = 0; cls < NCLS; cls++) {
        int s = g_boff[cam*NCLS + cls];
        int e = g_boff[cam*NCLS + cls + 1];
        int len = e - s;
        int lo = s + (len * sl)       / NSL;
        int hi = s + (len * (sl + 1)) / NSL;
        float a = 0.0f;
        for (int m = lo; m < hi; m++) {
            float4 db  = g_sbox[m];
            float2 as2 = g_sas[m];
            float lx = fmaxf(db.x, pb.x);
            float ly = fmaxf(db.y, pb.y);
            float rx = fminf(db.z, pb.z);
            float ry = fminf(db.w, pb.w);
            float wx = fmaxf(rx - lx, 0.0f);
            float wy = fmaxf(ry - ly, 0.0f);
            float inter = wx * wy;
            float uni   = as2.x + pa - inter;     // > 0: det area > 0, proj area > 0
            float iou   = __fdividef(inter, uni);
            a = fmaf(iou, as2.y, a);
        }
        acc[cls] = a;
    }
    float* outp = &g_part[(size_t)((cam*NSL + sl) * N + n) * NCLS];
    #pragma unroll
    for (int c = 0; c < NCLS; c++) outp[c] = acc[c];
}

// ============================================================================
// Kernel 6: fixed-order reduction over (cam, slice), mean, argmax
// ============================================================================
__global__ void finalize_kernel(float* __restrict__ out, int N) {
    int n = blockIdx.x * blockDim.x + threadIdx.x;
    if (n >= N) return;
    float probs[NCLS];
    #pragma unroll
    for (int c = 0; c < NCLS; c++) probs[c] = 0.0f;
    float vs = 0.0f;
    for (int cam = 0; cam < NCAM; cam++) {
        vs += g_validf[cam*N + n];
        for (int sl = 0; sl < NSL; sl++) {
            const float* p = &g_part[(size_t)((cam*NSL + sl) * N + n) * NCLS];
            #pragma unroll
            for (int c = 0; c < NCLS; c++) probs[c] += p[c];
        }
    }
    float denom = 1e-5f + vs;
    float best = __fdiv_rn(probs[0], denom);
    int bi = 0;
    #pragma unroll
    for (int c = 1; c < NCLS; c++) {
        float mv = __fdiv_rn(probs[c], denom);
        if (mv > best) { best = mv; bi = c; }
    }
    out[n]     = (float)(bi + 1);  // pred_labels
    out[N + n] = best;             // pred_scores (nan impossible: denom >= 1e-5)
}

// ============================================================================
extern "C" void kernel_launch(void* const* d_in, const int* in_sizes, int n_in,
                              void* d_out, int out_size) {
    const float* boxes = (const float*)d_in[0];
    const float* iam   = (const float*)d_in[1];
    const float* lam   = (const float*)d_in[2];
    const float* l2i   = (const float*)d_in[3];
    const float* dbox  = (const float*)d_in[4];
    const int*   dlab  = (const int*)  d_in[5];
    const float* dsc   = (const float*)d_in[6];
    const int*   dbat  = (const int*)  d_in[7];
    const int*   dcam  = (const int*)  d_in[8];
    int N = in_sizes[0] / 7;
    int M = in_sizes[4] / 4;
    if (N > NMAX) N = NMAX;
    if (M > MMAX) M = MMAX;
    float* out = (float*)d_out;

    proj_kernel   <<<(N + 127) / 128, 128>>>(boxes, iam, lam, l2i, N);
    compact_valid <<<NCAM, 256>>>(N);
    hist_kernel   <<<1, 256>>>(dlab, dbat, dcam, M);
    scatter_kernel<<<NCAM * NCLS, 256>>>(dbox, dlab, dsc, dbat, dcam, M);
    dim3 g((N + 255) / 256, NCAM, NSL);
    main_kernel   <<<g, 256>>>(N);
    finalize_kernel<<<(N + 255) / 256, 256>>>(out, N);
}

// round 3
// speedup vs baseline: 1.2623x; 1.2623x over previous
#include <cuda_runtime.h>

#define NMAX 4096
#define MMAX 8192
#define NCAM 6
#define NCLS 10
#define NSL  8
#define NBKT (NCAM * NCLS)
#define IMGW 1600
#define IMGH 900

// ---- device scratch (static; no allocs) ----
__device__ float4 g_proj  [NCAM * NMAX];
__device__ float  g_parea [NCAM * NMAX];
__device__ float  g_validf[NCAM * NMAX];
__device__ int    g_vlist [NCAM * NMAX];
__device__ int    g_vcount[NCAM];
__device__ int    g_boff  [NBKT + 1];
__device__ int    g_brank [NBKT];
__device__ float4 g_sbox  [MMAX];
__device__ float2 g_sas   [MMAX];   // (det_area, score)
__device__ float  g_part  [NCAM * NSL * NMAX * NCLS];  // partial class sums

// ============================================================================
// Kernel 0: zero the replay-carried atomic counters
// ============================================================================
__global__ void init_kernel() {
    int t = threadIdx.x;
    if (t < NCAM) g_vcount[t] = 0;
    if (t < NBKT) g_brank[t] = 0;
}

// ============================================================================
// Kernel 1: project 3D boxes -> per-camera 2D boxes + validity + valid-list
// ============================================================================
__global__ void proj_kernel(const float* __restrict__ boxes,
                            const float* __restrict__ iam,   // (1,6,4,4)
                            const float* __restrict__ lam,   // (1,4,4)
                            const float* __restrict__ l2i,   // (1,6,4,4)
                            int N) {
    int n = blockIdx.x * blockDim.x + threadIdx.x;
    if (n >= N) return;

    float bx = boxes[n*7+0], by = boxes[n*7+1], bz = boxes[n*7+2];
    float ddx = boxes[n*7+3], ddy = boxes[n*7+4], ddz = boxes[n*7+5];
    float yaw = boxes[n*7+6];
    float sn, cs;
    sincosf(yaw, &sn, &cs);

    // lidar aug: p = inv(R) @ (corner - t)
    float r00=lam[0], r01=lam[1], r02=lam[2],  t0=lam[3];
    float r10=lam[4], r11=lam[5], r12=lam[6],  t1=lam[7];
    float r20=lam[8], r21=lam[9], r22=lam[10], t2=lam[11];
    float A = r11*r22 - r12*r21;
    float B = r02*r21 - r01*r22;
    float C = r01*r12 - r02*r11;
    float D = r12*r20 - r10*r22;
    float E = r00*r22 - r02*r20;
    float F = r02*r10 - r00*r12;
    float G = r10*r21 - r11*r20;
    float H = r01*r20 - r00*r21;
    float I = r00*r11 - r01*r10;
    float det = r00*A + r01*D + r02*G;
    float id  = __fdiv_rn(1.0f, det);
    float i00=A*id, i01=B*id, i02=C*id;
    float i10=D*id, i11=E*id, i12=F*id;
    float i20=G*id, i21=H*id, i22=I*id;

    float px[8], py[8], pz[8];
    #pragma unroll
    for (int k = 0; k < 8; k++) {
        float lx = ((k & 1) ? 0.5f : -0.5f) * ddx;
        float ly = ((k & 2) ? 0.5f : -0.5f) * ddy;
        float lz = ((k & 4) ? 0.5f : -0.5f) * ddz;
        float wx = lx*cs - ly*sn + bx;
        float wy = lx*sn + ly*cs + by;
        float wz = lz + bz;
        float ax = wx - t0, ay = wy - t1, az = wz - t2;
        px[k] = i00*ax + i01*ay + i02*az;
        py[k] = i10*ax + i11*ay + i12*az;
        pz[k] = i20*ax + i21*ay + i22*az;
    }

    #pragma unroll
    for (int cam = 0; cam < NCAM; cam++) {
        const float* L  = l2i + cam*16;
        const float* Ai = iam + cam*16;
        int mnx =  0x7fffffff, mny =  0x7fffffff;
        int mxx = -0x7fffffff-1, mxy = -0x7fffffff-1;
        #pragma unroll
        for (int k = 0; k < 8; k++) {
            float cx  = L[0]*px[k] + L[1]*py[k] + L[2]*pz[k]  + L[3];
            float cyv = L[4]*px[k] + L[5]*py[k] + L[6]*pz[k]  + L[7];
            float cz  = L[8]*px[k] + L[9]*py[k] + L[10]*pz[k] + L[11];
            float z = fminf(fmaxf(cz, 1e-5f), 100000.0f);
            float x = __fdiv_rn(cx, z);     // IEEE: int truncation boundaries matter
            float y = __fdiv_rn(cyv, z);
            float ux = Ai[0]*x + Ai[1]*y + Ai[2]*z + Ai[3];
            float uy = Ai[4]*x + Ai[5]*y + Ai[6]*z + Ai[7];
            int ixi = (int)ux;  ixi = min(max(ixi, 0), IMGW);   // cvt.rzi saturates like ref
            int iyi = (int)uy;  iyi = min(max(iyi, 0), IMGH);
            mnx = min(mnx, ixi); mxx = max(mxx, ixi);
            mny = min(mny, iyi); mxy = max(mxy, iyi);
        }
        float fx1 = (float)mnx, fy1 = (float)mny;
        float fx2 = (float)mxx, fy2 = (float)mxy;
        bool valid = (mxx - mnx) > 0 && (mxy - mny) > 0;
        g_proj  [cam*N + n] = make_float4(fx1, fy1, fx2, fy2);
        g_parea [cam*N + n] = (fx2 - fx1) * (fy2 - fy1);
        g_validf[cam*N + n] = valid ? 1.0f : 0.0f;
        if (valid) {
            int pos = atomicAdd(&g_vcount[cam], 1);   // order irrelevant
            g_vlist[cam*N + pos] = n;
        }
    }
}

// ============================================================================
// Kernel 2: histogram + exclusive prefix over 60 (cam,class) buckets
//   single block, 1024 threads (6 strided rounds over M)
// ============================================================================
__global__ void hist_kernel(const int* __restrict__ lab, const int* __restrict__ bat,
                            const int* __restrict__ camix, int M) {
    __shared__ int h[NBKT];
    int tid = threadIdx.x;
    if (tid < NBKT) h[tid] = 0;
    __syncthreads();
    for (int m = tid; m < M; m += 1024) {
        int l = lab[m], b = bat[m], c = camix[m];
        if (b == 0 && l >= 1 && l <= NCLS && c >= 0 && c < NCAM)
            atomicAdd(&h[c * NCLS + l - 1], 1);
    }
    __syncthreads();
    if (tid == 0) {
        int s = 0;
        #pragma unroll
        for (int k = 0; k < NBKT; k++) { g_boff[k] = s; s += h[k]; }
        g_boff[NBKT] = s;
    }
}

// ============================================================================
// Kernel 3: one-pass scatter into bucketed order via atomic rank
// ============================================================================
__global__ void scatter_kernel(const float* __restrict__ dbox, const int* __restrict__ lab,
                               const float* __restrict__ dsc, const int* __restrict__ bat,
                               const int* __restrict__ camix, int M) {
    int m = blockIdx.x * blockDim.x + threadIdx.x;
    if (m >= M) return;
    int l = lab[m], b = bat[m], c = camix[m];
    if (!(b == 0 && l >= 1 && l <= NCLS && c >= 0 && c < NCAM)) return;
    int bkt = c * NCLS + l - 1;
    int r = g_boff[bkt] + atomicAdd(&g_brank[bkt], 1);
    float4 db = __ldg((const float4*)(dbox) + m);
    g_sbox[r] = db;
    g_sas[r]  = make_float2((db.z - db.x) * (db.w - db.y), dsc[m]);
}

// ============================================================================
// Kernel 4: main IoU-weighted class accumulation over valid (cam,box) pairs
// ============================================================================
__global__ void main_kernel(int N) {
    int cam = blockIdx.y;
    int sl  = blockIdx.z;
    int i   = blockIdx.x * blockDim.x + threadIdx.x;
    if (i >= g_vcount[cam]) return;
    int n = g_vlist[cam*N + i];

    float4 pb = g_proj [cam*N + n];
    float  pa = g_parea[cam*N + n];

    float acc[NCLS];
    #pragma unroll
    for (int cls = 0; cls < NCLS; cls++) {
        int s = g_boff[cam*NCLS + cls];
        int e = g_boff[cam*NCLS + cls + 1];
        int len = e - s;
        int lo = s + (len * sl)       / NSL;
        int hi = s + (len * (sl + 1)) / NSL;
        float a = 0.0f;
        for (int m = lo; m < hi; m++) {
            float4 db  = g_sbox[m];
            float2 as2 = g_sas[m];
            float lx = fmaxf(db.x, pb.x);
            float ly = fmaxf(db.y, pb.y);
            float rx = fminf(db.z, pb.z);
            float ry = fminf(db.w, pb.w);
            float wx = fmaxf(rx - lx, 0.0f);
            float wy = fmaxf(ry - ly, 0.0f);
            float inter = wx * wy;
            float uni   = as2.x + pa - inter;
            float iou   = __fdividef(inter, uni);
            a = fmaf(iou, as2.y, a);
        }
        acc[cls] = a;
    }
    float* outp = &g_part[(size_t)((cam*NSL + sl) * N + n) * NCLS];
    #pragma unroll
    for (int c = 0; c < NCLS; c++) outp[c] = acc[c];
}

// ============================================================================
// Kernel 5: fixed-order reduction over (cam, slice), mean, argmax
// ============================================================================
__global__ void finalize_kernel(float* __restrict__ out, int N) {
    int n = blockIdx.x * blockDim.x + threadIdx.x;
    if (n >= N) return;
    float probs[NCLS];
    #pragma unroll
    for (int c = 0; c < NCLS; c++) probs[c] = 0.0f;
    float vs = 0.0f;
    for (int cam = 0; cam < NCAM; cam++) {
        vs += g_validf[cam*N + n];
        for (int sl = 0; sl < NSL; sl++) {
            const float* p = &g_part[(size_t)((cam*NSL + sl) * N + n) * NCLS];
            #pragma unroll
            for (int c = 0; c < NCLS; c++) probs[c] += p[c];
        }
    }
    float denom = 1e-5f + vs;
    float best = __fdiv_rn(probs[0], denom);
    int bi = 0;
    #pragma unroll
    for (int c = 1; c < NCLS; c++) {
        float mv = __fdiv_rn(probs[c], denom);
        if (mv > best) { best = mv; bi = c; }
    }
    out[n]     = (float)(bi + 1);  // pred_labels
    out[N + n] = best;             // pred_scores
}

// ============================================================================
extern "C" void kernel_launch(void* const* d_in, const int* in_sizes, int n_in,
                              void* d_out, int out_size) {
    const float* boxes = (const float*)d_in[0];
    const float* iam   = (const float*)d_in[1];
    const float* lam   = (const float*)d_in[2];
    const float* l2i   = (const float*)d_in[3];
    const float* dbox  = (const float*)d_in[4];
    const int*   dlab  = (const int*)  d_in[5];
    const float* dsc   = (const float*)d_in[6];
    const int*   dbat  = (const int*)  d_in[7];
    const int*   dcam  = (const int*)  d_in[8];
    int N = in_sizes[0] / 7;
    int M = in_sizes[4] / 4;
    if (N > NMAX) N = NMAX;
    if (M > MMAX) M = MMAX;
    float* out = (float*)d_out;

    init_kernel   <<<1, 64>>>();
    proj_kernel   <<<(N + 127) / 128, 128>>>(boxes, iam, lam, l2i, N);
    hist_kernel   <<<1, 1024>>>(dlab, dbat, dcam, M);
    scatter_kernel<<<(M + 255) / 256, 256>>>(dbox, dlab, dsc, dbat, dcam, M);
    dim3 g((N + 255) / 256, NCAM, NSL);
    main_kernel   <<<g, 256>>>(N);
    finalize_kernel<<<(N + 255) / 256, 256>>>(out, N);
}

// round 4
// speedup vs baseline: 1.5288x; 1.2111x over previous
#include <cuda_runtime.h>

#define NCAM 6
#define NCLS 10
#define NSL  8
#define NBKT (NCAM * NCLS)
#define NMAX 4096
#define MMAX 8192
#define IMGW 1600
#define IMGH 900
#define NBLK 148
#define NTHR 256

// ---- device scratch (static; no allocs) ----
__device__ float4 g_proj  [NCAM * NMAX];
__device__ float  g_parea [NCAM * NMAX];
__device__ float  g_validf[NCAM * NMAX];
__device__ int    g_vlist [NCAM * NMAX];
__device__ int    g_vcount[NCAM];
__device__ int    g_bcnt  [NBKT];
__device__ int    g_brank [NBKT];
__device__ float4 g_sbox  [MMAX];
__device__ float2 g_sas   [MMAX];            // (det_area, score)
// class-major partials: [((cam*NSL+sl)*NCLS + c) * NMAX + n]
__device__ float  g_part  [NCAM * NSL * NCLS * NMAX];
__device__ unsigned          g_bar_count;     // static zero-init; self-resetting
__device__ volatile unsigned g_bar_epoch;     // grows monotonically across replays

// ---- software grid barrier (all NBLK blocks co-resident by construction) ----
__device__ __forceinline__ void grid_barrier(unsigned start, unsigned k) {
    __syncthreads();
    if (threadIdx.x == 0) {
        __threadfence();
        unsigned a = atomicAdd(&g_bar_count, 1u);
        if (a == (unsigned)gridDim.x - 1u) {
            atomicExch(&g_bar_count, 0u);
            __threadfence();
            atomicAdd((unsigned*)&g_bar_epoch, 1u);
        } else {
            while (g_bar_epoch - start < k) __nanosleep(32);
        }
        __threadfence();
    }
    __syncthreads();
}

__global__ __launch_bounds__(NTHR)
void fused_kernel(const float* __restrict__ boxes,
                  const float* __restrict__ iam,    // (1,6,4,4)
                  const float* __restrict__ lam,    // (1,4,4)
                  const float* __restrict__ l2i,    // (1,6,4,4)
                  const float* __restrict__ dbox,
                  const int*   __restrict__ dlab,
                  const float* __restrict__ dsc,
                  const int*   __restrict__ dbat,
                  const int*   __restrict__ dcam,
                  float* __restrict__ out,
                  int N, int M) {
    const int gtid = blockIdx.x * NTHR + threadIdx.x;
    const int T    = gridDim.x * NTHR;

    __shared__ unsigned s_start;
    __shared__ int s_cnt[NBKT];
    __shared__ int s_vc[NCAM];
    __shared__ int s_boff[NBKT + 1];
    __shared__ int s_vbase[NCAM + 1];

    if (threadIdx.x == 0) s_start = g_bar_epoch;   // before first arrive: safe
    __syncthreads();
    const unsigned start = s_start;

    // ======================= P1a: projection, (cam, box) items ==============
    for (int w = gtid; w < NCAM * N; w += T) {
        int cam = w / N;
        int n   = w - cam * N;
        const float* bp = boxes + n * 7;
        float bx = bp[0], by = bp[1], bz = bp[2];
        float ddx = bp[3], ddy = bp[4], ddz = bp[5];
        float yaw = bp[6];
        float sn, cs;
        sincosf(yaw, &sn, &cs);

        // lidar aug inverse (uniform across threads; cheap)
        float r00=lam[0], r01=lam[1], r02=lam[2],  t0=lam[3];
        float r10=lam[4], r11=lam[5], r12=lam[6],  t1=lam[7];
        float r20=lam[8], r21=lam[9], r22=lam[10], t2=lam[11];
        float A = r11*r22 - r12*r21;
        float B = r02*r21 - r01*r22;
        float C = r01*r12 - r02*r11;
        float D = r12*r20 - r10*r22;
        float E = r00*r22 - r02*r20;
        float F = r02*r10 - r00*r12;
        float G = r10*r21 - r11*r20;
        float H = r01*r20 - r00*r21;
        float I = r00*r11 - r01*r10;
        float det = r00*A + r01*D + r02*G;
        float id  = __fdiv_rn(1.0f, det);
        float i00=A*id, i01=B*id, i02=C*id;
        float i10=D*id, i11=E*id, i12=F*id;
        float i20=G*id, i21=H*id, i22=I*id;

        const float* L  = l2i + cam * 16;
        const float* Ai = iam + cam * 16;
        int mnx =  0x7fffffff, mny =  0x7fffffff;
        int mxx = -0x7fffffff-1, mxy = -0x7fffffff-1;
        #pragma unroll
        for (int k = 0; k < 8; k++) {
            float lx = ((k & 1) ? 0.5f : -0.5f) * ddx;
            float ly = ((k & 2) ? 0.5f : -0.5f) * ddy;
            float lz = ((k & 4) ? 0.5f : -0.5f) * ddz;
            float wx = lx*cs - ly*sn + bx;
            float wy = lx*sn + ly*cs + by;
            float wz = lz + bz;
            float ax = wx - t0, ay = wy - t1, az = wz - t2;
            float px = i00*ax + i01*ay + i02*az;
            float py = i10*ax + i11*ay + i12*az;
            float pz = i20*ax + i21*ay + i22*az;

            float cx  = L[0]*px + L[1]*py + L[2]*pz  + L[3];
            float cyv = L[4]*px + L[5]*py + L[6]*pz  + L[7];
            float cz  = L[8]*px + L[9]*py + L[10]*pz + L[11];
            float z = fminf(fmaxf(cz, 1e-5f), 100000.0f);
            float x = __fdiv_rn(cx, z);     // IEEE: truncation boundaries must match ref
            float y = __fdiv_rn(cyv, z);
            float ux = Ai[0]*x + Ai[1]*y + Ai[2]*z + Ai[3];
            float uy = Ai[4]*x + Ai[5]*y + Ai[6]*z + Ai[7];
            int ixi = (int)ux;  ixi = min(max(ixi, 0), IMGW);   // cvt.rzi saturates like ref
            int iyi = (int)uy;  iyi = min(max(iyi, 0), IMGH);
            mnx = min(mnx, ixi); mxx = max(mxx, ixi);
            mny = min(mny, iyi); mxy = max(mxy, iyi);
        }
        float fx1 = (float)mnx, fy1 = (float)mny;
        float fx2 = (float)mxx, fy2 = (float)mxy;
        bool valid = (mxx - mnx) > 0 && (mxy - mny) > 0;
        g_proj  [cam*N + n] = make_float4(fx1, fy1, fx2, fy2);
        g_parea [cam*N + n] = (fx2 - fx1) * (fy2 - fy1);
        g_validf[cam*N + n] = valid ? 1.0f : 0.0f;
        if (valid) {
            int pos = atomicAdd(&g_vcount[cam], 1);   // order irrelevant
            g_vlist[cam*N + pos] = n;
        }
    }

    // ======================= P1b: det histogram ==============================
    for (int m = gtid; m < M; m += T) {
        int l = dlab[m], b = dbat[m], c = dcam[m];
        if (b == 0 && l >= 1 && l <= NCLS && c >= 0 && c < NCAM)
            atomicAdd(&g_bcnt[c * NCLS + l - 1], 1);
    }

    grid_barrier(start, 1);

    // ======================= P2: block-local prefixes (no barrier) ==========
    if (threadIdx.x < NBKT) s_cnt[threadIdx.x] = g_bcnt[threadIdx.x];
    if (threadIdx.x < NCAM) s_vc[threadIdx.x]  = g_vcount[threadIdx.x];
    __syncthreads();
    if (threadIdx.x == 0) {
        int s = 0;
        #pragma unroll
        for (int k = 0; k < NBKT; k++) { s_boff[k] = s; s += s_cnt[k]; }
        s_boff[NBKT] = s;
        int p = 0;
        #pragma unroll
        for (int c = 0; c < NCAM; c++) { s_vbase[c] = p; p += s_vc[c]; }
        s_vbase[NCAM] = p;
    }
    __syncthreads();

    // ======================= P3: scatter dets into bucket order =============
    for (int m = gtid; m < M; m += T) {
        int l = dlab[m], b = dbat[m], c = dcam[m];
        if (b == 0 && l >= 1 && l <= NCLS && c >= 0 && c < NCAM) {
            int bkt = c * NCLS + l - 1;
            int r = s_boff[bkt] + atomicAdd(&g_brank[bkt], 1);
            float4 db = __ldg((const float4*)dbox + m);
            g_sbox[r] = db;
            g_sas[r]  = make_float2((db.z - db.x) * (db.w - db.y), dsc[m]);
        }
    }

    grid_barrier(start, 2);

    // ======================= P4: main IoU class accumulation ================
    {
        const int W = s_vbase[NCAM] * NSL;
        for (int w = gtid; w < W; w += T) {
            int cam = 0;
            while (w >= s_vbase[cam + 1] * NSL) cam++;
            int vc    = s_vbase[cam + 1] - s_vbase[cam];
            int local = w - s_vbase[cam] * NSL;
            int sl    = local / vc;
            int i     = local - sl * vc;
            int n     = g_vlist[cam*N + i];

            float4 pb = g_proj [cam*N + n];
            float  pa = g_parea[cam*N + n];

            float acc[NCLS];
            #pragma unroll
            for (int cls = 0; cls < NCLS; cls++) {
                int s2  = s_boff[cam*NCLS + cls];
                int e2  = s_boff[cam*NCLS + cls + 1];
                int len = e2 - s2;
                int lo = s2 + (len * sl)       / NSL;
                int hi = s2 + (len * (sl + 1)) / NSL;
                float a = 0.0f;
                for (int m = lo; m < hi; m++) {
                    float4 db  = g_sbox[m];
                    float2 as2 = g_sas[m];
                    float lx = fmaxf(db.x, pb.x);
                    float ly = fmaxf(db.y, pb.y);
                    float rx = fminf(db.z, pb.z);
                    float ry = fminf(db.w, pb.w);
                    float wx = fmaxf(rx - lx, 0.0f);
                    float wy = fmaxf(ry - ly, 0.0f);
                    float inter = wx * wy;
                    float uni   = as2.x + pa - inter;
                    float iou   = __fdividef(inter, uni);
                    a = fmaf(iou, as2.y, a);
                }
                acc[cls] = a;
            }
            float* outp = &g_part[(size_t)((cam*NSL + sl) * NCLS) * NMAX + n];
            #pragma unroll
            for (int c = 0; c < NCLS; c++) outp[(size_t)c * NMAX] = acc[c];
        }
    }

    grid_barrier(start, 3);

    // ======================= P5: finalize + counter reset ===================
    for (int n = gtid; n < N; n += T) {
        float probs[NCLS];
        #pragma unroll
        for (int c = 0; c < NCLS; c++) probs[c] = 0.0f;
        float vs = 0.0f;
        #pragma unroll
        for (int cam = 0; cam < NCAM; cam++) vs += g_validf[cam*N + n];
        for (int cs = 0; cs < NCAM * NSL; cs++) {
            const float* p = &g_part[(size_t)(cs * NCLS) * NMAX + n];
            #pragma unroll
            for (int c = 0; c < NCLS; c++) probs[c] += p[(size_t)c * NMAX];
        }
        float denom = 1e-5f + vs;
        float best = __fdiv_rn(probs[0], denom);
        int bi = 0;
        #pragma unroll
        for (int c = 1; c < NCLS; c++) {
            float mv = __fdiv_rn(probs[c], denom);
            if (mv > best) { best = mv; bi = c; }
        }
        out[n]     = (float)(bi + 1);  // pred_labels
        out[N + n] = best;             // pred_scores
    }

    // restore replay-carried counters for the next launch (graph replay)
    if (gtid < NBKT) { g_bcnt[gtid] = 0; g_brank[gtid] = 0; }
    if (gtid < NCAM) g_vcount[gtid] = 0;
}

// ============================================================================
extern "C" void kernel_launch(void* const* d_in, const int* in_sizes, int n_in,
                              void* d_out, int out_size) {
    const float* boxes = (const float*)d_in[0];
    const float* iam   = (const float*)d_in[1];
    const float* lam   = (const float*)d_in[2];
    const float* l2i   = (const float*)d_in[3];
    const float* dbox  = (const float*)d_in[4];
    const int*   dlab  = (const int*)  d_in[5];
    const float* dsc   = (const float*)d_in[6];
    const int*   dbat  = (const int*)  d_in[7];
    const int*   dcam  = (const int*)  d_in[8];
    int N = in_sizes[0] / 7;
    int M = in_sizes[4] / 4;
    if (N > NMAX) N = NMAX;
    if (M > MMAX) M = MMAX;
    float* out = (float*)d_out;

    fused_kernel<<<NBLK, NTHR>>>(boxes, iam, lam, l2i, dbox, dlab, dsc,
                                 dbat, dcam, out, N, M);
}

// round 5
// speedup vs baseline: 2.2223x; 1.4536x over previous
#include <cuda_runtime.h>

#define NCAM 6
#define NCLS 10
#define NBKT (NCAM * NCLS)
#define NMAX 4096
#define MMAX 8192
#define IMGW 1600
#define IMGH 900
#define NBLK 148
#define NTHR 512
#define MAXSL 16

// ---- device scratch (static; no allocs) ----
__device__ float4 g_proj  [NCAM * NMAX];
__device__ float  g_parea [NCAM * NMAX];
__device__ float  g_validf[NCAM * NMAX];
__device__ int    g_vlist [NCAM * NMAX];
__device__ int    g_vcount[NCAM];
__device__ int    g_bcnt  [NBKT];
__device__ int    g_brank [NBKT];
__device__ float4 g_sbox  [MMAX];
__device__ float2 g_sas   [MMAX];            // (det_area, score)
__device__ float  g_probs [NCLS * NMAX];     // class-major accumulators
__device__ unsigned          g_bar_count;    // static zero-init; self-resetting
__device__ volatile unsigned g_bar_epoch;    // grows monotonically across replays

// ---- software grid barrier (all NBLK blocks co-resident by construction) ----
__device__ __forceinline__ void grid_barrier(unsigned start, unsigned k) {
    __syncthreads();
    if (threadIdx.x == 0) {
        __threadfence();
        unsigned a = atomicAdd(&g_bar_count, 1u);
        if (a == (unsigned)gridDim.x - 1u) {
            atomicExch(&g_bar_count, 0u);
            __threadfence();
            atomicAdd((unsigned*)&g_bar_epoch, 1u);
        } else {
            while (g_bar_epoch - start < k) __nanosleep(32);
        }
        __threadfence();
    }
    __syncthreads();
}

__global__ __launch_bounds__(NTHR)
void fused_kernel(const float* __restrict__ boxes,
                  const float* __restrict__ iam,    // (1,6,4,4)
                  const float* __restrict__ lam,    // (1,4,4)
                  const float* __restrict__ l2i,    // (1,6,4,4)
                  const float* __restrict__ dbox,
                  const int*   __restrict__ dlab,
                  const float* __restrict__ dsc,
                  const int*   __restrict__ dbat,
                  const int*   __restrict__ dcam,
                  float* __restrict__ out,
                  int N, int M) {
    const int gtid = blockIdx.x * NTHR + threadIdx.x;
    const int T    = gridDim.x * NTHR;

    __shared__ unsigned s_start;
    __shared__ int s_cnt[NBKT];
    __shared__ int s_vc[NCAM];
    __shared__ int s_boff[NBKT + 1];
    __shared__ int s_vbase[NCAM + 1];
    __shared__ int s_SL;

    if (threadIdx.x == 0) s_start = g_bar_epoch;   // read before any arrive
    __syncthreads();
    const unsigned start = s_start;

    // zero the class accumulators (consumed in P4/P5 of THIS launch)
    for (int k = gtid; k < NCLS * NMAX; k += T) g_probs[k] = 0.0f;

    // ---- uniform lidar-aug inverse, hoisted out of the item loop ----
    float i00,i01,i02,i10,i11,i12,i20,i21,i22,t0,t1,t2;
    {
        float r00=lam[0], r01=lam[1], r02=lam[2];  t0=lam[3];
        float r10=lam[4], r11=lam[5], r12=lam[6];  t1=lam[7];
        float r20=lam[8], r21=lam[9], r22=lam[10]; t2=lam[11];
        float A = r11*r22 - r12*r21;
        float B = r02*r21 - r01*r22;
        float C = r01*r12 - r02*r11;
        float D = r12*r20 - r10*r22;
        float E = r00*r22 - r02*r20;
        float F = r02*r10 - r00*r12;
        float G = r10*r21 - r11*r20;
        float H = r01*r20 - r00*r21;
        float I = r00*r11 - r01*r10;
        float det = r00*A + r01*D + r02*G;
        float id  = __fdiv_rn(1.0f, det);
        i00=A*id; i01=B*id; i02=C*id;
        i10=D*id; i11=E*id; i12=F*id;
        i20=G*id; i21=H*id; i22=I*id;
    }

    // ======================= P1a: projection, (cam, box) items ==============
    for (int w = gtid; w < NCAM * N; w += T) {
        int cam = w / N;
        int n   = w - cam * N;
        const float* bp = boxes + n * 7;
        float bx = bp[0], by = bp[1], bz = bp[2];
        float ddx = bp[3], ddy = bp[4], ddz = bp[5];
        float yaw = bp[6];
        float sn, cs;
        sincosf(yaw, &sn, &cs);

        const float* L  = l2i + cam * 16;
        const float* Ai = iam + cam * 16;
        int mnx =  0x7fffffff, mny =  0x7fffffff;
        int mxx = -0x7fffffff-1, mxy = -0x7fffffff-1;
        #pragma unroll
        for (int k = 0; k < 8; k++) {
            float lx = ((k & 1) ? 0.5f : -0.5f) * ddx;
            float ly = ((k & 2) ? 0.5f : -0.5f) * ddy;
            float lz = ((k & 4) ? 0.5f : -0.5f) * ddz;
            float wx = lx*cs - ly*sn + bx;
            float wy = lx*sn + ly*cs + by;
            float wz = lz + bz;
            float ax = wx - t0, ay = wy - t1, az = wz - t2;
            float px = i00*ax + i01*ay + i02*az;
            float py = i10*ax + i11*ay + i12*az;
            float pz = i20*ax + i21*ay + i22*az;

            float cx  = L[0]*px + L[1]*py + L[2]*pz  + L[3];
            float cyv = L[4]*px + L[5]*py + L[6]*pz  + L[7];
            float cz  = L[8]*px + L[9]*py + L[10]*pz + L[11];
            float z = fminf(fmaxf(cz, 1e-5f), 100000.0f);
            float x = __fdiv_rn(cx, z);     // IEEE: truncation boundaries must match ref
            float y = __fdiv_rn(cyv, z);
            float ux = Ai[0]*x + Ai[1]*y + Ai[2]*z + Ai[3];
            float uy = Ai[4]*x + Ai[5]*y + Ai[6]*z + Ai[7];
            int ixi = (int)ux;  ixi = min(max(ixi, 0), IMGW);   // cvt.rzi saturates like ref
            int iyi = (int)uy;  iyi = min(max(iyi, 0), IMGH);
            mnx = min(mnx, ixi); mxx = max(mxx, ixi);
            mny = min(mny, iyi); mxy = max(mxy, iyi);
        }
        float fx1 = (float)mnx, fy1 = (float)mny;
        float fx2 = (float)mxx, fy2 = (float)mxy;
        bool valid = (mxx - mnx) > 0 && (mxy - mny) > 0;
        g_proj  [cam*N + n] = make_float4(fx1, fy1, fx2, fy2);
        g_parea [cam*N + n] = (fx2 - fx1) * (fy2 - fy1);
        g_validf[cam*N + n] = valid ? 1.0f : 0.0f;
        if (valid) {
            int pos = atomicAdd(&g_vcount[cam], 1);   // order irrelevant
            g_vlist[cam*N + pos] = n;
        }
    }

    // ======================= P1b: det histogram ==============================
    for (int m = gtid; m < M; m += T) {
        int l = dlab[m], b = dbat[m], c = dcam[m];
        if (b == 0 && l >= 1 && l <= NCLS && c >= 0 && c < NCAM)
            atomicAdd(&g_bcnt[c * NCLS + l - 1], 1);
    }

    grid_barrier(start, 1);

    // ======================= P2: block-local prefixes (no barrier) ==========
    if (threadIdx.x < NBKT) s_cnt[threadIdx.x] = g_bcnt[threadIdx.x];
    if (threadIdx.x < NCAM) s_vc[threadIdx.x]  = g_vcount[threadIdx.x];
    __syncthreads();
    if (threadIdx.x == 0) {
        int s = 0;
        #pragma unroll
        for (int k = 0; k < NBKT; k++) { s_boff[k] = s; s += s_cnt[k]; }
        s_boff[NBKT] = s;
        int p = 0;
        #pragma unroll
        for (int c = 0; c < NCAM; c++) { s_vbase[c] = p; p += s_vc[c]; }
        s_vbase[NCAM] = p;
        int vt = p > 0 ? p : 1;
        int sl = T / vt;
        if (sl < 1) sl = 1;
        if (sl > MAXSL) sl = MAXSL;
        s_SL = sl;
    }
    __syncthreads();

    // ======================= P3: scatter dets into bucket order =============
    for (int m = gtid; m < M; m += T) {
        int l = dlab[m], b = dbat[m], c = dcam[m];
        if (b == 0 && l >= 1 && l <= NCLS && c >= 0 && c < NCAM) {
            int bkt = c * NCLS + l - 1;
            int r = s_boff[bkt] + atomicAdd(&g_brank[bkt], 1);
            float4 db = __ldg((const float4*)dbox + m);
            g_sbox[r] = db;
            g_sas[r]  = make_float2((db.z - db.x) * (db.w - db.y), dsc[m]);
        }
    }

    grid_barrier(start, 2);

    // ======================= P4: main IoU class accumulation ================
    {
        const int SL   = s_SL;
        const int vtot = s_vbase[NCAM];
        const int W    = vtot * SL;
        for (int w = gtid; w < W; w += T) {
            int sl = w / vtot;            // consecutive threads -> consecutive pairs
            int p  = w - sl * vtot;
            int cam = 0;
            while (p >= s_vbase[cam + 1]) cam++;
            int i  = p - s_vbase[cam];
            int n  = g_vlist[cam*N + i];

            float4 pb = g_proj [cam*N + n];
            float  pa = g_parea[cam*N + n];

            #pragma unroll
            for (int cls = 0; cls < NCLS; cls++) {
                int s2  = s_boff[cam*NCLS + cls];
                int e2  = s_boff[cam*NCLS + cls + 1];
                int len = e2 - s2;
                int lo = s2 + (len * sl)       / SL;
                int hi = s2 + (len * (sl + 1)) / SL;
                float a = 0.0f;
                for (int m = lo; m < hi; m++) {
                    float4 db  = g_sbox[m];
                    float2 as2 = g_sas[m];
                    float lx = fmaxf(db.x, pb.x);
                    float ly = fmaxf(db.y, pb.y);
                    float rx = fminf(db.z, pb.z);
                    float ry = fminf(db.w, pb.w);
                    float wx = fmaxf(rx - lx, 0.0f);
                    float wy = fmaxf(ry - ly, 0.0f);
                    float inter = wx * wy;
                    float uni   = as2.x + pa - inter;
                    float iou   = __fdividef(inter, uni);
                    a = fmaf(iou, as2.y, a);
                }
                if (a != 0.0f) atomicAdd(&g_probs[cls * NMAX + n], a);
            }
        }
    }

    grid_barrier(start, 3);

    // ======================= P5: finalize + counter reset ===================
    for (int n = gtid; n < N; n += T) {
        float vs = 0.0f;
        #pragma unroll
        for (int cam = 0; cam < NCAM; cam++) vs += g_validf[cam*N + n];
        float denom = 1e-5f + vs;
        float best = __fdiv_rn(g_probs[n], denom);
        int bi = 0;
        #pragma unroll
        for (int c = 1; c < NCLS; c++) {
            float mv = __fdiv_rn(g_probs[c * NMAX + n], denom);
            if (mv > best) { best = mv; bi = c; }
        }
        out[n]     = (float)(bi + 1);  // pred_labels
        out[N + n] = best;             // pred_scores
    }

    // restore replay-carried counters for the next launch (graph replay)
    if (gtid < NBKT) { g_bcnt[gtid] = 0; g_brank[gtid] = 0; }
    if (gtid < NCAM) g_vcount[gtid] = 0;
}

// ============================================================================
extern "C" void kernel_launch(void* const* d_in, const int* in_sizes, int n_in,
                              void* d_out, int out_size) {
    const float* boxes = (const float*)d_in[0];
    const float* iam   = (const float*)d_in[1];
    const float* lam   = (const float*)d_in[2];
    const float* l2i   = (const float*)d_in[3];
    const float* dbox  = (const float*)d_in[4];
    const int*   dlab  = (const int*)  d_in[5];
    const float* dsc   = (const float*)d_in[6];
    const int*   dbat  = (const int*)  d_in[7];
    const int*   dcam  = (const int*)  d_in[8];
    int N = in_sizes[0] / 7;
    int M = in_sizes[4] / 4;
    if (N > NMAX) N = NMAX;
    if (M > MMAX) M = MMAX;
    float* out = (float*)d_out;

    fused_kernel<<<NBLK, NTHR>>>(boxes, iam, lam, l2i, dbox, dlab, dsc,
                                 dbat, dcam, out, N, M);
}